// round 2
// baseline (speedup 1.0000x reference)
#include <cuda_runtime.h>
#include <cstdint>

// Problem shape (fixed by dataset): x:(32,512,64,64) f32, weight:(1,1,3,3), k=256
#define BB 32
#define NN 512
#define HH 64
#define WW 64
#define IMG_ELEMS (HH * WW)          // 4096

// Scratch (no cudaMalloc allowed)
__device__ float2 g_scores[BB * NN];
__device__ int    g_order[BB * NN];

// ---------------------------------------------------------------------------
// Phase 1: per-image conv score, register-resident sliding window, NO smem.
// 16 lanes (half-warp) per image; lane li owns output columns 4li..4li+3.
// Per row: one LDG.128 (own 4 cols) + one LDG.64 (next 2 cols, L1 hit).
// grid = B*N/8 blocks, 128 threads (8 images per block).
// ---------------------------------------------------------------------------
__global__ __launch_bounds__(128) void score_kernel(
    const float* __restrict__ x, const float* __restrict__ w,
    float2* __restrict__ scores)
{
    const int t   = threadIdx.x;
    const int li  = t & 15;                      // lane within image group
    const int img = blockIdx.x * 8 + (t >> 4);
    const bool edge = (li == 15);                // owns cols 60..63; no cols 64,65

    const float wc = w[0];   // corners
    const float wE = w[1];   // edges
    const float wm = w[4];   // center

    const float* base = x + (size_t)img * IMG_ELEMS + li * 4;

    // Sliding horizontal sums for the two previous rows:
    //   Ha[j] = x[row][c]+x[row][c+2], Hm[j] = x[row][c+1]  for c = 4li+j
    float Ha1[4], Hm1[4], Ha2[4], Hm2[4];
    float s = 0.f, e = 0.f;

#pragma unroll 4
    for (int rr = 0; rr < HH; rr++) {
        const float* rp = base + rr * WW;
        float4 v4 = *reinterpret_cast<const float4*>(rp);
        float x4 = 0.f, x5 = 0.f;
        if (!edge) {
            float2 v2 = *reinterpret_cast<const float2*>(rp + 4);
            x4 = v2.x; x5 = v2.y;
        }
        float Hac[4], Hmc[4];
        Hac[0] = v4.x + v4.z;  Hmc[0] = v4.y;
        Hac[1] = v4.y + v4.w;  Hmc[1] = v4.z;
        Hac[2] = v4.z + x4;    Hmc[2] = v4.w;
        Hac[3] = v4.w + x5;    Hmc[3] = x4;

        if (rr >= 2) {
#pragma unroll
            for (int j = 0; j < 4; j++) {
                float s1 = Ha2[j] + Hac[j];
                float s2 = (Hm2[j] + Hmc[j]) + Ha1[j];
                float v  = fmaf(wc, s1, fmaf(wE, s2, wm * Hm1[j]));
                float av = fabsf(v);
                if (j >= 2 && edge) av = 0.f;     // cols 62,63 are not valid outputs
                // Fast2Sum compensated accumulate (guarded from fast-math)
                float tt  = __fadd_rn(s, av);
                float err = __fadd_rn(__fsub_rn(s, tt), av);
                e = __fadd_rn(e, err);
                s = tt;
            }
        }
#pragma unroll
        for (int j = 0; j < 4; j++) {
            Ha2[j] = Ha1[j]; Hm2[j] = Hm1[j];
            Ha1[j] = Hac[j]; Hm1[j] = Hmc[j];
        }
    }

    // Half-warp (width=16) double-float reduction with exact TwoSum
#pragma unroll
    for (int off = 8; off; off >>= 1) {
        float s2 = __shfl_down_sync(0xffffffffu, s, off, 16);
        float e2 = __shfl_down_sync(0xffffffffu, e, off, 16);
        float tt  = __fadd_rn(s, s2);
        float z   = __fsub_rn(tt, s);
        float err = __fadd_rn(__fsub_rn(s, __fsub_rn(tt, z)), __fsub_rn(s2, z));
        e = __fadd_rn(__fadd_rn(e, e2), err);
        s = tt;
    }

    if (li == 0) {
        // Renormalize so lexicographic (hi, lo) compare == value compare
        float h = __fadd_rn(s, e);
        float l = __fadd_rn(__fsub_rn(s, h), e);
        scores[img] = make_float2(h, l);
    }
}

// ---------------------------------------------------------------------------
// Phase 2: exact top-k ranking per batch (descending, ties -> lower index first)
// grid = B blocks, N threads
// ---------------------------------------------------------------------------
__global__ __launch_bounds__(NN) void topk_kernel(
    const float2* __restrict__ scores, int* __restrict__ order, int k)
{
    __shared__ float2 sc[NN];
    const int b = blockIdx.x;
    const int n = threadIdx.x;
    sc[n] = scores[b * NN + n];
    __syncthreads();

    const float2 mine = sc[n];
    int rank = 0;
#pragma unroll 8
    for (int m = 0; m < NN; m++) {
        float2 o = sc[m];
        bool better = (o.x > mine.x) ||
                      (o.x == mine.x && (o.y > mine.y ||
                                         (o.y == mine.y && m < n)));
        rank += better;
    }
    if (rank < k) order[b * k + rank] = n;
}

// ---------------------------------------------------------------------------
// Phase 3: gather selected images; 8 loads in flight before any store (MLP=8)
// grid = B*k blocks, 128 threads
// ---------------------------------------------------------------------------
__global__ __launch_bounds__(128) void gather_kernel(
    const float* __restrict__ x, const int* __restrict__ order,
    float* __restrict__ out, int k)
{
    const int bj = blockIdx.x;
    const int b  = bj / k;
    const int n  = order[bj];
    const float4* src = reinterpret_cast<const float4*>(
        x + ((size_t)(b * NN + n)) * IMG_ELEMS);
    float4* dst = reinterpret_cast<float4*>(out + (size_t)bj * IMG_ELEMS);

    float4 r[8];
#pragma unroll
    for (int i = 0; i < 8; i++) r[i] = src[threadIdx.x + i * 128];
#pragma unroll
    for (int i = 0; i < 8; i++) dst[threadIdx.x + i * 128] = r[i];
}

// ---------------------------------------------------------------------------
extern "C" void kernel_launch(void* const* d_in, const int* in_sizes, int n_in,
                              void* d_out, int out_size)
{
    const float* x = (const float*)d_in[0];
    const float* w = (const float*)d_in[1];
    float* out = (float*)d_out;

    const int k = out_size / (BB * IMG_ELEMS);   // = 256

    score_kernel<<<(BB * NN) / 8, 128>>>(x, w, g_scores);
    topk_kernel<<<BB, NN>>>(g_scores, g_order, k);
    gather_kernel<<<BB * k, 128>>>(x, g_order, out, k);
}

// round 3
// speedup vs baseline: 1.0582x; 1.0582x over previous
#include <cuda_runtime.h>
#include <cstdint>

// Problem shape (fixed): x:(32,512,64,64) f32, weight:(1,1,3,3), k=256
#define BB 32
#define NN 512
#define HH 64
#define WW 64
#define IMG_ELEMS (HH * WW)          // 4096

// Scratch (no cudaMalloc allowed)
__device__ float2 g_scores[BB * NN];
__device__ int    g_order[BB * NN];

// ---------------------------------------------------------------------------
// Phase 1: warp-per-image conv score. Lane li owns cols 2li,2li+1 for all rows.
// One LDG.64 per lane per row (warp = full 256B row, each element read once);
// horizontal neighbors via 2x SHFL.DOWN. Vertical 3-tap window in registers.
// grid = B*N/8, block = 256 (8 warps = 8 images).
// ---------------------------------------------------------------------------
__global__ __launch_bounds__(256) void score_kernel(
    const float* __restrict__ x, const float* __restrict__ w,
    float2* __restrict__ scores)
{
    const int li   = threadIdx.x & 31;
    const int img  = blockIdx.x * 8 + (threadIdx.x >> 5);
    const bool tail = (li == 31);                 // cols 62,63: no valid outputs

    const float wc = w[0];   // corners
    const float wE = w[1];   // edges
    const float wm = w[4];   // center

    const float* base = x + (size_t)img * IMG_ELEMS + li * 2;

    // Sliding horizontal sums of the two previous rows:
    //   Ha[j] = x[row][c] + x[row][c+2],  Hm[j] = x[row][c+1],  c = 2li+j
    float Ha1[2], Hm1[2], Ha2[2], Hm2[2];
    float s = 0.f, e = 0.f;

#pragma unroll 4
    for (int rr = 0; rr < HH; rr++) {
        float2 v = *reinterpret_cast<const float2*>(base + rr * WW);
        float nx = __shfl_down_sync(0xffffffffu, v.x, 1);  // x[2li+2]
        float ny = __shfl_down_sync(0xffffffffu, v.y, 1);  // x[2li+3]

        float Hac[2], Hmc[2];
        Hac[0] = v.x + nx;  Hmc[0] = v.y;
        Hac[1] = v.y + ny;  Hmc[1] = nx;

        if (rr >= 2) {
#pragma unroll
            for (int j = 0; j < 2; j++) {
                float s1 = Ha2[j] + Hac[j];
                float s2 = (Hm2[j] + Hmc[j]) + Ha1[j];
                float vv = fmaf(wc, s1, fmaf(wE, s2, wm * Hm1[j]));
                float av = fabsf(vv);
                if (tail) av = 0.f;
                // Fast2Sum compensated accumulate (guarded from fast-math)
                float tt  = __fadd_rn(s, av);
                float err = __fadd_rn(__fsub_rn(s, tt), av);
                e = __fadd_rn(e, err);
                s = tt;
            }
        }
        Ha2[0] = Ha1[0]; Hm2[0] = Hm1[0]; Ha1[0] = Hac[0]; Hm1[0] = Hmc[0];
        Ha2[1] = Ha1[1]; Hm2[1] = Hm1[1]; Ha1[1] = Hac[1]; Hm1[1] = Hmc[1];
    }

    // Full-warp double-float reduction (exact TwoSum)
#pragma unroll
    for (int off = 16; off; off >>= 1) {
        float s2 = __shfl_down_sync(0xffffffffu, s, off);
        float e2 = __shfl_down_sync(0xffffffffu, e, off);
        float tt  = __fadd_rn(s, s2);
        float z   = __fsub_rn(tt, s);
        float err = __fadd_rn(__fsub_rn(s, __fsub_rn(tt, z)), __fsub_rn(s2, z));
        e = __fadd_rn(__fadd_rn(e, e2), err);
        s = tt;
    }

    if (li == 0) {
        // Renormalize so lexicographic (hi, lo) compare == value compare
        float h = __fadd_rn(s, e);
        float l = __fadd_rn(__fsub_rn(s, h), e);
        scores[img] = make_float2(h, l);
    }
}

// ---------------------------------------------------------------------------
// Phase 2: exact top-k ranking per batch (descending, ties -> lower index first)
// ---------------------------------------------------------------------------
__global__ __launch_bounds__(NN) void topk_kernel(
    const float2* __restrict__ scores, int* __restrict__ order, int k)
{
    __shared__ float2 sc[NN];
    const int b = blockIdx.x;
    const int n = threadIdx.x;
    sc[n] = scores[b * NN + n];
    __syncthreads();

    const float2 mine = sc[n];
    int rank = 0;
#pragma unroll 8
    for (int m = 0; m < NN; m++) {
        float2 o = sc[m];
        bool better = (o.x > mine.x) ||
                      (o.x == mine.x && (o.y > mine.y ||
                                         (o.y == mine.y && m < n)));
        rank += better;
    }
    if (rank < k) order[b * k + rank] = n;
}

// ---------------------------------------------------------------------------
// Phase 3: gather selected images; 4 loads in flight before stores, 256 thr.
// ---------------------------------------------------------------------------
__global__ __launch_bounds__(256) void gather_kernel(
    const float* __restrict__ x, const int* __restrict__ order,
    float* __restrict__ out, int k)
{
    const int bj = blockIdx.x;
    const int b  = bj / k;
    const int n  = __ldg(&order[bj]);
    const float4* src = reinterpret_cast<const float4*>(
        x + ((size_t)(b * NN + n)) * IMG_ELEMS);
    float4* dst = reinterpret_cast<float4*>(out + (size_t)bj * IMG_ELEMS);

    float4 r[4];
#pragma unroll
    for (int i = 0; i < 4; i++) r[i] = src[threadIdx.x + i * 256];
#pragma unroll
    for (int i = 0; i < 4; i++) dst[threadIdx.x + i * 256] = r[i];
}

// ---------------------------------------------------------------------------
extern "C" void kernel_launch(void* const* d_in, const int* in_sizes, int n_in,
                              void* d_out, int out_size)
{
    const float* x = (const float*)d_in[0];
    const float* w = (const float*)d_in[1];
    float* out = (float*)d_out;

    const int k = out_size / (BB * IMG_ELEMS);   // = 256

    score_kernel<<<(BB * NN) / 8, 256>>>(x, w, g_scores);
    topk_kernel<<<BB, NN>>>(g_scores, g_order, k);
    gather_kernel<<<BB * k, 256>>>(x, g_order, out, k);
}

// round 4
// speedup vs baseline: 1.1943x; 1.1286x over previous
#include <cuda_runtime.h>
#include <cstdint>

// Problem shape (fixed): x:(32,512,64,64) f32, weight:(1,1,3,3), k=256
#define BB 32
#define NN 512
#define HH 64
#define WW 64
#define IMG_ELEMS (HH * WW)          // 4096

// Scratch (no cudaMalloc allowed)
__device__ float2 g_scores[BB * NN];
__device__ int    g_order[BB * NN];

// ---------------------------------------------------------------------------
// Phase 1: warp-per-image conv score. Lane li owns cols 2li,2li+1.
// Rows processed in chunks of 8: all 8 LDG.64 issued before compute (MLP=8).
// Horizontal neighbors via 2x SHFL; vertical 3-tap window in registers.
// Per-row Fast2Sum fold keeps the score ordering-accurate to ~1e-5.
// grid = B*N/8, block = 256 (8 warps = 8 images).
// ---------------------------------------------------------------------------
__global__ __launch_bounds__(256) void score_kernel(
    const float* __restrict__ x, const float* __restrict__ w,
    float2* __restrict__ scores)
{
    const int li   = threadIdx.x & 31;
    const int img  = blockIdx.x * 8 + (threadIdx.x >> 5);
    const bool tail = (li == 31);                 // cols 62,63: invalid outputs

    const float wc = w[0];   // corners
    const float wE = w[1];   // edges
    const float wm = w[4];   // center

    const float2* b2 = reinterpret_cast<const float2*>(
        x + (size_t)img * IMG_ELEMS) + li;        // stride 32 float2 per row

    // Sliding horizontal sums of the two previous rows:
    //   Ha[j] = x[row][c] + x[row][c+2],  Hm[j] = x[row][c+1],  c = 2li+j
    float Ha1[2], Hm1[2], Ha2[2], Hm2[2];
    float s = 0.f, e = 0.f;

    float2 v[8];

    // ---- chunk 0: rows 0..7 (prime with rows 0,1; compute rows 2..7) ----
#pragma unroll
    for (int i = 0; i < 8; i++) v[i] = b2[i * 32];

    {
        float nx = __shfl_down_sync(0xffffffffu, v[0].x, 1);
        float ny = __shfl_down_sync(0xffffffffu, v[0].y, 1);
        Ha2[0] = v[0].x + nx;  Hm2[0] = v[0].y;
        Ha2[1] = v[0].y + ny;  Hm2[1] = nx;
        nx = __shfl_down_sync(0xffffffffu, v[1].x, 1);
        ny = __shfl_down_sync(0xffffffffu, v[1].y, 1);
        Ha1[0] = v[1].x + nx;  Hm1[0] = v[1].y;
        Ha1[1] = v[1].y + ny;  Hm1[1] = nx;
    }

#define DO_ROW(vv)                                                          \
    {                                                                       \
        float nx = __shfl_down_sync(0xffffffffu, (vv).x, 1);                \
        float ny = __shfl_down_sync(0xffffffffu, (vv).y, 1);                \
        float Hac0 = (vv).x + nx, Hmc0 = (vv).y;                            \
        float Hac1 = (vv).y + ny, Hmc1 = nx;                                \
        float s1a = Ha2[0] + Hac0;                                          \
        float s2a = (Hm2[0] + Hmc0) + Ha1[0];                               \
        float va  = fmaf(wc, s1a, fmaf(wE, s2a, wm * Hm1[0]));              \
        float s1b = Ha2[1] + Hac1;                                          \
        float s2b = (Hm2[1] + Hmc1) + Ha1[1];                               \
        float vb  = fmaf(wc, s1b, fmaf(wE, s2b, wm * Hm1[1]));              \
        float row = fabsf(va) + fabsf(vb);                                  \
        if (tail) row = 0.f;                                                \
        float tt  = __fadd_rn(s, row);                                      \
        e = __fadd_rn(e, __fadd_rn(__fsub_rn(s, tt), row));                 \
        s = tt;                                                             \
        Ha2[0] = Ha1[0]; Hm2[0] = Hm1[0]; Ha1[0] = Hac0; Hm1[0] = Hmc0;     \
        Ha2[1] = Ha1[1]; Hm2[1] = Hm1[1]; Ha1[1] = Hac1; Hm1[1] = Hmc1;     \
    }

#pragma unroll
    for (int i = 2; i < 8; i++) DO_ROW(v[i]);

    // ---- chunks 1..7: rows 8c..8c+7, all computed ----
    for (int c = 1; c < 8; c++) {
#pragma unroll
        for (int i = 0; i < 8; i++) v[i] = b2[(c * 8 + i) * 32];
#pragma unroll
        for (int i = 0; i < 8; i++) DO_ROW(v[i]);
    }
#undef DO_ROW

    // Full-warp double-float reduction (exact TwoSum)
#pragma unroll
    for (int off = 16; off; off >>= 1) {
        float s2 = __shfl_down_sync(0xffffffffu, s, off);
        float e2 = __shfl_down_sync(0xffffffffu, e, off);
        float tt  = __fadd_rn(s, s2);
        float z   = __fsub_rn(tt, s);
        float err = __fadd_rn(__fsub_rn(s, __fsub_rn(tt, z)), __fsub_rn(s2, z));
        e = __fadd_rn(__fadd_rn(e, e2), err);
        s = tt;
    }

    if (li == 0) {
        // Renormalize so lexicographic (hi, lo) compare == value compare
        float h = __fadd_rn(s, e);
        float l = __fadd_rn(__fsub_rn(s, h), e);
        scores[img] = make_float2(h, l);
    }
}

// ---------------------------------------------------------------------------
// Phase 2: exact top-k ranking per batch (descending, ties -> lower index first)
// ---------------------------------------------------------------------------
__global__ __launch_bounds__(NN) void topk_kernel(
    const float2* __restrict__ scores, int* __restrict__ order, int k)
{
    __shared__ float2 sc[NN];
    const int b = blockIdx.x;
    const int n = threadIdx.x;
    sc[n] = scores[b * NN + n];
    __syncthreads();

    const float2 mine = sc[n];
    int rank = 0;
#pragma unroll 8
    for (int m = 0; m < NN; m++) {
        float2 o = sc[m];
        bool better = (o.x > mine.x) ||
                      (o.x == mine.x && (o.y > mine.y ||
                                         (o.y == mine.y && m < n)));
        rank += better;
    }
    if (rank < k) order[b * k + rank] = n;
}

// ---------------------------------------------------------------------------
// Phase 3: gather selected images. 8 float4 loads in flight per thread before
// any store. Blocks run in REVERSE order: the score kernel streamed x in
// ascending order, so L2 still holds the tail of x -> early gather blocks hit.
// grid = B*k blocks, 128 threads.
// ---------------------------------------------------------------------------
__global__ __launch_bounds__(128) void gather_kernel(
    const float* __restrict__ x, const int* __restrict__ order,
    float* __restrict__ out, int k)
{
    const int bj = gridDim.x - 1 - blockIdx.x;    // reversed for L2 reuse
    const int b  = bj / k;
    const int n  = __ldg(&order[bj]);
    const float4* src = reinterpret_cast<const float4*>(
        x + ((size_t)(b * NN + n)) * IMG_ELEMS);
    float4* dst = reinterpret_cast<float4*>(out + (size_t)bj * IMG_ELEMS);

    float4 r[8];
#pragma unroll
    for (int i = 0; i < 8; i++) r[i] = src[threadIdx.x + i * 128];
#pragma unroll
    for (int i = 0; i < 8; i++) dst[threadIdx.x + i * 128] = r[i];
}

// ---------------------------------------------------------------------------
extern "C" void kernel_launch(void* const* d_in, const int* in_sizes, int n_in,
                              void* d_out, int out_size)
{
    const float* x = (const float*)d_in[0];
    const float* w = (const float*)d_in[1];
    float* out = (float*)d_out;

    const int k = out_size / (BB * IMG_ELEMS);   // = 256

    score_kernel<<<(BB * NN) / 8, 256>>>(x, w, g_scores);
    topk_kernel<<<BB, NN>>>(g_scores, g_order, k);
    gather_kernel<<<BB * k, 128>>>(x, g_order, out, k);
}